// round 7
// baseline (speedup 1.0000x reference)
#include <cuda_runtime.h>
#include <cuda_bf16.h>
#include <cstdint>
#include <cstring>

// ============================================================
// Problem constants
// ============================================================
static constexpr int SEQ   = 80;
static constexpr int EMB   = 100;
static constexpr int ROWS  = 32;    // batch rows per CTA
static constexpr int NCTA  = 128;   // 4096 / 32
static constexpr int THREADS = 256; // 8 warps: (rt 0..1) x (ug 0..3)

// ---- Shared memory layout (bytes). Strides are odd multiples of 16B ----
// weight tiles are [n=256][k] row-major bf16 (B operand, ldmatrix non-trans)
static constexpr int SX_W1 = 240;  // k=112 (x:100 + bias@100 + pad), 120 el
static constexpr int SX_U1 = 144;  // k=64, 72 el
static constexpr int SX_W2 = 176;  // k=80 (h1:64 + bias@64 + pad), 88 el
static constexpr int SX_U2 = 144;  // k=64
static constexpr int OFF_W1 = 0;                         // 256*240 = 61440
static constexpr int OFF_U1 = OFF_W1 + 256 * SX_W1;      // 61440
static constexpr int OFF_W2 = OFF_U1 + 256 * SX_U1;      // 98304
static constexpr int OFF_U2 = OFF_W2 + 256 * SX_W2;      // 143360
static constexpr int OFF_X  = OFF_U2 + 256 * SX_U2;      // 180224  x: [32][240B]
static constexpr int OFF_H1 = OFF_X  + ROWS * SX_W1;     // 187904  h1: 2x[32][176B]
static constexpr int OFF_H2 = OFF_H1 + 2 * ROWS * SX_W2; // 199168  h2: 2x[32][144B]
static constexpr int OFF_WD = OFF_H2 + 2 * ROWS * SX_U2; // 208384  64 f32
static constexpr int OFF_BD = OFF_WD + 256;              // 208640
static constexpr int OFF_RED = OFF_BD + 16;              // 208656  [32][4] f32
static constexpr int SMEM_TOTAL = OFF_RED + 512 + 16;    // 209184 -> pad
static constexpr int SMEM_ALLOC = 209408;

// ============================================================
// Helpers
// ============================================================
__device__ __forceinline__ uint32_t smem_to_u32(const void* smem_ptr) {
    uint32_t addr;
    asm("{ .reg .u64 tmp; cvta.to.shared.u64 tmp, %1; cvt.u32.u64 %0, tmp; }"
        : "=r"(addr) : "l"(smem_ptr));
    return addr;
}
__device__ __forceinline__ float tanhx(float x) {
    float y;
    asm("tanh.approx.f32 %0, %1;" : "=f"(y) : "f"(x));
    return y;
}
__device__ __forceinline__ float sigx(float x) {
    return fmaf(tanhx(0.5f * x), 0.5f, 0.5f);
}
__device__ __forceinline__ uint32_t packbf2(float lo, float hi) {
    __nv_bfloat162 v = __floats2bfloat162_rn(lo, hi);
    uint32_t u;
    memcpy(&u, &v, 4);
    return u;
}

__device__ __forceinline__ void ldsm_x4(uint32_t addr, uint32_t& r0, uint32_t& r1,
                                        uint32_t& r2, uint32_t& r3) {
    asm volatile("ldmatrix.sync.aligned.m8n8.x4.shared.b16 {%0,%1,%2,%3}, [%4];"
                 : "=r"(r0), "=r"(r1), "=r"(r2), "=r"(r3) : "r"(addr));
}

__device__ __forceinline__ void mma16816(float* d, uint32_t a0, uint32_t a1,
                                         uint32_t a2, uint32_t a3,
                                         uint32_t b0, uint32_t b1) {
    asm volatile(
        "mma.sync.aligned.m16n8k16.row.col.f32.bf16.bf16.f32 "
        "{%0,%1,%2,%3}, {%4,%5,%6,%7}, {%8,%9}, {%0,%1,%2,%3};"
        : "+f"(d[0]), "+f"(d[1]), "+f"(d[2]), "+f"(d[3])
        : "r"(a0), "r"(a1), "r"(a2), "r"(a3), "r"(b0), "r"(b1));
}

// One GEMM term: acc[16 rows x 64 cols for this warp's (RB,UB)] +=
//   A[RB..RB+15, 16k per step] * B^T tile ([n][k] row-major smem).
// acc layout: acc[gi*8 + nt*4 + j], gi=gate, nt=n-subtile(8 cols), j=frag elem.
template <int KSTEPS>
__device__ __forceinline__ void do_term(uint32_t aBase, int aStride,
                                        uint32_t bBase, int bStride,
                                        int RB, int UB, float* acc, int lane) {
    const int lrow = lane & 15;
    const int lk   = (lane >> 4) << 3;
#pragma unroll
    for (int ks = 0; ks < KSTEPS; ks++) {
        uint32_t a0, a1, a2, a3;
        ldsm_x4(aBase + (RB + lrow) * aStride + (ks * 16 + lk) * 2, a0, a1, a2, a3);
#pragma unroll
        for (int gi = 0; gi < 4; gi++) {
            uint32_t r0, r1, r2, r3;
            ldsm_x4(bBase + (gi * 64 + UB + lrow) * bStride + (ks * 16 + lk) * 2,
                    r0, r1, r2, r3);
            mma16816(acc + gi * 8 + 0, a0, a1, a2, a3, r0, r2);  // units UB..UB+7
            mma16816(acc + gi * 8 + 4, a0, a1, a2, a3, r1, r3);  // units UB+8..15
        }
    }
}

// Gate epilogue: acc (i,f,g,o) -> c update, h -> smem (bf16), optional dense dot.
__device__ __forceinline__ void epilogue(const float* acc, float* c,
                                         uint32_t hBase, int hStride,
                                         int RB, int UB, int lane,
                                         const float* wd_s, float* pr) {
    const int g = lane >> 2, tg = lane & 3;
#pragma unroll
    for (int nt = 0; nt < 2; nt++) {
#pragma unroll
        for (int rh = 0; rh < 2; rh++) {
            float hv[2];
#pragma unroll
            for (int uj = 0; uj < 2; uj++) {
                const int off = nt * 4 + rh * 2 + uj;
                float zi = acc[0 + off], zf = acc[8 + off];
                float zg = acc[16 + off], zo = acc[24 + off];
                float cc = sigx(zf) * c[off] + sigx(zi) * tanhx(zg);
                c[off] = cc;
                hv[uj] = sigx(zo) * tanhx(cc);
            }
            const int row = RB + rh * 8 + g;
            const int u   = UB + nt * 8 + 2 * tg;
            uint32_t pk = packbf2(hv[0], hv[1]);
            asm volatile("st.shared.b32 [%0], %1;"
                         :: "r"(hBase + row * hStride + u * 2), "r"(pk));
            if (wd_s) pr[rh] += hv[0] * wd_s[u] + hv[1] * wd_s[u + 1];
        }
    }
}

// ============================================================
// Fused kernel: 1 CTA = 32 batch rows, full sequence, 2 layers + dense head
// ============================================================
__global__ void __launch_bounds__(THREADS)
lstm_fused_kernel(const int* __restrict__ tokens,
                  const float* __restrict__ emb,
                  const float* __restrict__ W1, const float* __restrict__ U1,
                  const float* __restrict__ b1,
                  const float* __restrict__ W2, const float* __restrict__ U2,
                  const float* __restrict__ b2,
                  const float* __restrict__ Wd, const float* __restrict__ bd,
                  float* __restrict__ out) {
    extern __shared__ char smem[];
    const uint32_t sb = smem_to_u32(smem);
    const int tid  = threadIdx.x;
    const int wid  = tid >> 5;
    const int lane = tid & 31;
    const int rt = wid >> 2, ug = wid & 3;
    const int RB = rt * 16, UB = ug * 16;

    // ---- zero all smem ----
    for (int i = tid * 16; i < SMEM_TOTAL; i += THREADS * 16)
        *reinterpret_cast<uint4*>(smem + i) = make_uint4(0, 0, 0, 0);
    __syncthreads();

    // ---- stage weights: [n][k] bf16 (transposed), biases as extra k-column ----
    __nv_bfloat16* sm_bf = reinterpret_cast<__nv_bfloat16*>(smem);
    for (int i = tid; i < 256 * 101; i += THREADS) {      // W1t + b1 row
        int k = i / 256, n = i - k * 256;
        float v = (k < EMB) ? W1[k * 256 + n] : b1[n];
        *reinterpret_cast<__nv_bfloat16*>(smem + OFF_W1 + n * SX_W1 + k * 2) =
            __float2bfloat16(v);
    }
    for (int i = tid; i < 256 * 64; i += THREADS) {       // U1t
        int k = i >> 8, n = i & 255;
        *reinterpret_cast<__nv_bfloat16*>(smem + OFF_U1 + n * SX_U1 + k * 2) =
            __float2bfloat16(U1[k * 256 + n]);
    }
    for (int i = tid; i < 256 * 65; i += THREADS) {       // W2t + b2 row
        int k = i / 256, n = i - k * 256;
        float v = (k < 64) ? W2[k * 256 + n] : b2[n];
        *reinterpret_cast<__nv_bfloat16*>(smem + OFF_W2 + n * SX_W2 + k * 2) =
            __float2bfloat16(v);
    }
    for (int i = tid; i < 256 * 64; i += THREADS) {       // U2t
        int k = i >> 8, n = i & 255;
        *reinterpret_cast<__nv_bfloat16*>(smem + OFF_U2 + n * SX_U2 + k * 2) =
            __float2bfloat16(U2[k * 256 + n]);
    }
    if (tid < 64) *reinterpret_cast<float*>(smem + OFF_WD + 4 * tid) = Wd[tid];
    if (tid == 64) *reinterpret_cast<float*>(smem + OFF_BD) = bd[0];
    // static ones-columns: x[row][100], h1 (both parities)[row][64]
    if (tid < ROWS)
        *reinterpret_cast<__nv_bfloat16*>(smem + OFF_X + tid * SX_W1 + EMB * 2) =
            __float2bfloat16(1.0f);
    if (tid < 2 * ROWS) {
        int p = tid >> 5, r = tid & 31;
        *reinterpret_cast<__nv_bfloat16*>(smem + OFF_H1 + p * ROWS * SX_W2 +
                                          r * SX_W2 + 64 * 2) = __float2bfloat16(1.0f);
    }

    // ---- x gather helpers ----
    const int xrow = tid >> 3, seg = tid & 7;
    const int grow = blockIdx.x * ROWS + xrow;

    // gather x[t=0]
    {
        int tok = tokens[grow * SEQ + 0];
        const float4* ep = reinterpret_cast<const float4*>(emb + (size_t)tok * EMB);
        float4 v0 = ep[seg], v1 = ep[seg + 8], v2 = ep[seg + 16];
        uint32_t xb = sb + OFF_X + xrow * SX_W1;
        uint2 u;
        u.x = packbf2(v0.x, v0.y); u.y = packbf2(v0.z, v0.w);
        asm volatile("st.shared.v2.b32 [%0], {%1,%2};" :: "r"(xb + seg * 8), "r"(u.x), "r"(u.y));
        u.x = packbf2(v1.x, v1.y); u.y = packbf2(v1.z, v1.w);
        asm volatile("st.shared.v2.b32 [%0], {%1,%2};" :: "r"(xb + (seg + 8) * 8), "r"(u.x), "r"(u.y));
        u.x = packbf2(v2.x, v2.y); u.y = packbf2(v2.z, v2.w);
        asm volatile("st.shared.v2.b32 [%0], {%1,%2};" :: "r"(xb + (seg + 16) * 8), "r"(u.x), "r"(u.y));
        if (seg == 0) {
            float4 v3 = ep[24];
            u.x = packbf2(v3.x, v3.y); u.y = packbf2(v3.z, v3.w);
            asm volatile("st.shared.v2.b32 [%0], {%1,%2};" :: "r"(xb + 24 * 8), "r"(u.x), "r"(u.y));
        }
    }
    __syncthreads();

    const float* wd_s = reinterpret_cast<const float*>(smem + OFF_WD);
    float* red = reinterpret_cast<float*>(smem + OFF_RED);

    float c1[8], c2[8];
#pragma unroll
    for (int q = 0; q < 8; q++) { c1[q] = 0.f; c2[q] = 0.f; }
    float pr[2] = {0.f, 0.f};
    float acc[32];
    int p = 0;

#pragma unroll 1
    for (int t = 0; t < SEQ; t++) {
        // -- prefetch x[t+1] into registers (latency hidden by L1 mma) --
        float4 v0, v1, v2, v3;
        if (t + 1 < SEQ) {
            int tok = tokens[grow * SEQ + t + 1];
            const float4* ep = reinterpret_cast<const float4*>(emb + (size_t)tok * EMB);
            v0 = ep[seg]; v1 = ep[seg + 8]; v2 = ep[seg + 16];
            if (seg == 0) v3 = ep[24];
        }

        // -------- Layer 1: z = x@W1t + h1[p]@U1t (+b1 via ones col) --------
#pragma unroll
        for (int q = 0; q < 32; q++) acc[q] = 0.f;
        do_term<7>(sb + OFF_X, SX_W1, sb + OFF_W1, SX_W1, RB, UB, acc, lane);
        do_term<4>(sb + OFF_H1 + p * ROWS * SX_W2, SX_W2, sb + OFF_U1, SX_U1,
                   RB, UB, acc, lane);
        __syncthreads();  // all warps done reading x[t], h-bufs stable

        // L1 epilogue -> h1 into buf p^1 ; store x[t+1]
        epilogue(acc, c1, sb + OFF_H1 + (p ^ 1) * ROWS * SX_W2, SX_W2,
                 RB, UB, lane, nullptr, pr);
        if (t + 1 < SEQ) {
            uint32_t xb = sb + OFF_X + xrow * SX_W1;
            uint2 u;
            u.x = packbf2(v0.x, v0.y); u.y = packbf2(v0.z, v0.w);
            asm volatile("st.shared.v2.b32 [%0], {%1,%2};" :: "r"(xb + seg * 8), "r"(u.x), "r"(u.y));
            u.x = packbf2(v1.x, v1.y); u.y = packbf2(v1.z, v1.w);
            asm volatile("st.shared.v2.b32 [%0], {%1,%2};" :: "r"(xb + (seg + 8) * 8), "r"(u.x), "r"(u.y));
            u.x = packbf2(v2.x, v2.y); u.y = packbf2(v2.z, v2.w);
            asm volatile("st.shared.v2.b32 [%0], {%1,%2};" :: "r"(xb + (seg + 16) * 8), "r"(u.x), "r"(u.y));
            if (seg == 0) {
                u.x = packbf2(v3.x, v3.y); u.y = packbf2(v3.z, v3.w);
                asm volatile("st.shared.v2.b32 [%0], {%1,%2};" :: "r"(xb + 24 * 8), "r"(u.x), "r"(u.y));
            }
        }
        __syncthreads();  // h1 new + x[t+1] visible

        // -------- Layer 2: z = h1[p^1]@W2t (+b2) + h2[p]@U2t --------
#pragma unroll
        for (int q = 0; q < 32; q++) acc[q] = 0.f;
        do_term<5>(sb + OFF_H1 + (p ^ 1) * ROWS * SX_W2, SX_W2, sb + OFF_W2, SX_W2,
                   RB, UB, acc, lane);
        do_term<4>(sb + OFF_H2 + p * ROWS * SX_U2, SX_U2, sb + OFF_U2, SX_U2,
                   RB, UB, acc, lane);

        // L2 epilogue -> h2 into buf p^1 (safe: no reader until next-step barriers)
        epilogue(acc, c2, sb + OFF_H2 + (p ^ 1) * ROWS * SX_U2, SX_U2,
                 RB, UB, lane, (t == SEQ - 1) ? wd_s : nullptr, pr);
        p ^= 1;
    }

    // -------- Dense head: out = sigmoid(h2_last @ Wd + bd) --------
    // reduce pr over tg (lanes differing in bits 0,1 share rows, different units)
#pragma unroll
    for (int rh = 0; rh < 2; rh++) {
        pr[rh] += __shfl_xor_sync(0xffffffffu, pr[rh], 1);
        pr[rh] += __shfl_xor_sync(0xffffffffu, pr[rh], 2);
    }
    if ((lane & 3) == 0) {
        int g = lane >> 2;
#pragma unroll
        for (int rh = 0; rh < 2; rh++)
            red[(RB + rh * 8 + g) * 4 + ug] = pr[rh];
    }
    __syncthreads();
    if (tid < ROWS) {
        float bdv = *reinterpret_cast<const float*>(smem + OFF_BD);
        float v = red[tid * 4 + 0] + red[tid * 4 + 1] +
                  red[tid * 4 + 2] + red[tid * 4 + 3] + bdv;
        out[blockIdx.x * ROWS + tid] = sigx(v);
    }
}

// ============================================================
// Launch
// ============================================================
extern "C" void kernel_launch(void* const* d_in, const int* in_sizes, int n_in,
                              void* d_out, int out_size) {
    const int*   tokens = (const int*)d_in[0];
    const float* emb    = (const float*)d_in[1];
    const float* W1     = (const float*)d_in[2];
    const float* U1     = (const float*)d_in[3];
    const float* b1     = (const float*)d_in[4];
    const float* W2     = (const float*)d_in[5];
    const float* U2     = (const float*)d_in[6];
    const float* b2     = (const float*)d_in[7];
    const float* Wd     = (const float*)d_in[8];
    const float* bd     = (const float*)d_in[9];
    float* out = (float*)d_out;

    cudaFuncSetAttribute(lstm_fused_kernel,
                         cudaFuncAttributeMaxDynamicSharedMemorySize, SMEM_ALLOC);
    lstm_fused_kernel<<<NCTA, THREADS, SMEM_ALLOC>>>(
        tokens, emb, W1, U1, b1, W2, U2, b2, Wd, bd, out);
}